// round 7
// baseline (speedup 1.0000x reference)
#include <cuda_runtime.h>

// Problem constants (fixed by the reference generator)
#define NGR   64
#define NPG   96
#define NODES (NGR*NPG)       // 6144
#define HID   64
#define INF   32
#define EF    16
#define DEG   8
#define EDGES (NODES*DEG)     // 49152
#define EPG   (NPG*DEG)       // 768
#define PAIRS (NODES*NPG)     // 589824

// ---------------- scratch (static device globals) ---------------------------
__device__ float g_M1[INF*HID];
__device__ float g_M2[EF*HID];
__device__ float g_bn[HID];
__device__ float g_be[HID];
__device__ float g_WA[INF*HID];
__device__ float g_WB[INF*HID];
__device__ float g_WC[EF*HID];
__device__ float g_biasA[HID];
__device__ float g_biasB[HID];
__device__ float g_biasC[HID];
__device__ float g_vecA[NODES*HID];
__device__ float g_vecBT[NGR*HID*NPG];   // [graph][m][j]  m-major transposed
__device__ float g_Ce[(size_t)EDGES*HID];

// ---------------- K1a: first composition stage (parallel) -------------------
__global__ void prep1_kernel(const float* __restrict__ W_atom, const float* __restrict__ b_atom,
                             const float* __restrict__ W_bond, const float* __restrict__ b_bond,
                             const float* __restrict__ W_node, const float* __restrict__ b_node,
                             const float* __restrict__ W_edge, const float* __restrict__ b_edge)
{
    int i = blockIdx.x * blockDim.x + threadIdx.x;
    if (i < INF*HID) {
        int r = i >> 6, k = i & 63;
        float s = 0.f;
        #pragma unroll 8
        for (int j = 0; j < HID; j++) s = fmaf(W_atom[r*HID+j], W_node[j*HID+k], s);
        g_M1[i] = s;
    } else if (i < INF*HID + EF*HID) {
        int i2 = i - INF*HID;
        int r = i2 >> 6, k = i2 & 63;
        float s = 0.f;
        #pragma unroll 8
        for (int j = 0; j < HID; j++) s = fmaf(W_bond[r*HID+j], W_edge[j*HID+k], s);
        g_M2[i2] = s;
    } else if (i < INF*HID + EF*HID + HID) {
        int k = i - (INF*HID + EF*HID);
        float s = b_node[k];
        #pragma unroll 8
        for (int j = 0; j < HID; j++) s = fmaf(b_atom[j], W_node[j*HID+k], s);
        g_bn[k] = s;
    } else if (i < INF*HID + EF*HID + 2*HID) {
        int k = i - (INF*HID + EF*HID + HID);
        float s = b_edge[k];
        #pragma unroll 8
        for (int j = 0; j < HID; j++) s = fmaf(b_bond[j], W_edge[j*HID+k], s);
        g_be[k] = s;
    }
}

// ---------------- K1b: fold into W1 blocks (parallel) ------------------------
__global__ void prep2_kernel(const float* __restrict__ W1, const float* __restrict__ b1)
{
    int i = blockIdx.x * blockDim.x + threadIdx.x;
    if (i < INF*HID) {
        int r = i >> 6, k = i & 63;
        float s = 0.f;
        #pragma unroll 8
        for (int j = 0; j < HID; j++) s = fmaf(g_M1[r*HID+j], W1[j*HID + k], s);
        g_WA[i] = s;
    } else if (i < 2*INF*HID) {
        int i2 = i - INF*HID;
        int r = i2 >> 6, k = i2 & 63;
        float s = 0.f;
        #pragma unroll 8
        for (int j = 0; j < HID; j++) s = fmaf(g_M1[r*HID+j], W1[(64+j)*HID + k], s);
        g_WB[i2] = s;
    } else if (i < 2*INF*HID + EF*HID) {
        int i2 = i - 2*INF*HID;
        int r = i2 >> 6, k = i2 & 63;
        float s = 0.f;
        #pragma unroll 8
        for (int j = 0; j < HID; j++) s = fmaf(g_M2[r*HID+j], W1[(128+j)*HID + k], s);
        g_WC[i2] = s;
    } else if (i < 2*INF*HID + EF*HID + HID) {
        int k = i - (2*INF*HID + EF*HID);
        float sa = b1[k], sb = 0.f, sc = 0.f;
        #pragma unroll 4
        for (int j = 0; j < HID; j++) {
            sa = fmaf(g_bn[j], W1[j*HID + k], sa);
            sb = fmaf(g_bn[j], W1[(64+j)*HID + k], sb);
            sc = fmaf(g_be[j], W1[(128+j)*HID + k], sc);
        }
        g_biasA[k] = sa;
        g_biasB[k] = sb;
        g_biasC[k] = sc;
    }
}

// ---------------- K2: fused per-node + per-edge layer-1 partials -------------
#define NODE_BLOCKS (NODES/2)
#define EDGE_BLOCKS (EDGES/4)
__global__ void encode_kernel(const float* __restrict__ x, const float* __restrict__ ea)
{
    if (blockIdx.x < NODE_BLOCKS) {
        __shared__ float xr[2][INF];
        int half = threadIdx.x >> 7;
        int t    = threadIdx.x & 127;
        int node = blockIdx.x*2 + half;
        if (t < INF) xr[half][t] = x[node*INF + t];
        __syncthreads();
        int k = t & 63;
        const float* W = (t < 64) ? g_WA : g_WB;
        float s = (t < 64) ? g_biasA[k] : g_biasB[k];
        #pragma unroll
        for (int f = 0; f < INF; f++) s = fmaf(xr[half][f], W[f*HID + k], s);
        if (t < 64) {
            g_vecA[node*HID + k] = s;
        } else {
            int gg = node / NPG, lj = node - gg*NPG;
            g_vecBT[gg*(HID*NPG) + k*NPG + lj] = s;     // transposed store
        }
    } else {
        __shared__ float er[4][EF];
        int b   = blockIdx.x - NODE_BLOCKS;
        int grp = threadIdx.x >> 6;
        int k   = threadIdx.x & 63;
        int e   = b * 4 + grp;
        if (k < EF) er[grp][k] = ea[e*EF + k];
        __syncthreads();
        float s = g_biasC[k];
        #pragma unroll
        for (int f = 0; f < EF; f++) s = fmaf(er[grp][f], g_WC[f*HID + k], s);
        g_Ce[(size_t)e*HID + k] = s;
    }
}

// ---------------- K3: fused pairwise MLP, register-tiled GEMM ---------------
#define W2PITCH 72

#define FMA4(acc, a, b) \
    acc.x = fmaf(a, b.x, acc.x); \
    acc.y = fmaf(a, b.y, acc.y); \
    acc.z = fmaf(a, b.z, acc.z); \
    acc.w = fmaf(a, b.w, acc.w);

__global__ void __launch_bounds__(192, 3)
pair_kernel(const int* __restrict__ edge_index,
            const float* __restrict__ W2, const float* __restrict__ b2,
            const float* __restrict__ W3, const float* __restrict__ b3,
            float* __restrict__ out)
{
    extern __shared__ float s[];
    float* H0   = s;                         // [2][64][96]
    float* W2s  = s + 2*64*96;               // [64][72]
    float* Au_s = W2s + 64*W2PITCH;          // [2][64]
    float* W3s  = Au_s + 128;                // [64]
    float* b2s  = W3s + 64;                  // [64]
    long long* elist = (long long*)(b2s + 64);   // [2][96]
    int* e0s    = (int*)(elist + 2*96);          // [2][96]
    int* e1s    = e0s + 2*96;                    // [2][96]
    int* nms    = e1s + 2*96;                    // [2][96]
    int* ecount = nms + 2*96;                    // [2]

    const int tid = threadIdx.x;
    const int h   = tid / 96;
    const int lt  = tid - h*96;
    const int u   = blockIdx.x*2 + h;
    const int g   = u / NPG;
    const int lu  = u - g*NPG;
    float* H0h = H0 + h*64*96;
    long long* el = elist + h*96;
    int* nmsH = nms + h*96;
    int* e0sH = e0s + h*96;
    int* e1sH = e1s + h*96;

    if (lt == 0) ecount[h] = 0;
    for (int idx = tid; idx < 64*64; idx += 192) {
        int m = idx >> 6, k = idx & 63;
        W2s[m*W2PITCH + k] = W2[idx];
    }
    if (tid < 64) { W3s[tid] = W3[tid]; b2s[tid] = b2[tid]; }
    if (lt < 64) Au_s[h*64 + lt] = g_vecA[(size_t)u*HID + lt];
    __syncthreads();

    // gather this node's out-edges
    const int* srcA = edge_index;
    const int* dstA = edge_index + EDGES;
    for (int e = g*EPG + lt; e < (g+1)*EPG; e += 96) {
        if (srcA[e] == u) {
            int p = atomicAdd(&ecount[h], 1);
            if (p < 96) el[p] = ((long long)e << 32) | (unsigned)(dstA[e] - g*NPG);
        }
    }
    __syncthreads();
    const int ec = min(ecount[h], 96);
    if (lt == 0) {      // deterministic order
        for (int a = 1; a < ec; a++) {
            long long v = el[a]; int b = a - 1;
            while (b >= 0 && el[b] > v) { el[b+1] = el[b]; b--; }
            el[b+1] = v;
        }
    }
    __syncthreads();

    // per-column edge-match table (thread lt owns column j = lt)
    {
        int e0 = -1, e1 = -1, nm = 0;
        for (int q = 0; q < ec; q++) {
            long long pk = el[q];
            if ((int)(pk & 0xffffffffLL) == lt) {
                int e = (int)(pk >> 32);
                if (nm == 0) e0 = e; else if (nm == 1) e1 = e;
                nm++;
            }
        }
        e0sH[lt] = e0;
        e1sH[lt] = e1;
        nmsH[lt] = nm;
    }
    __syncthreads();

    // ---- build H0: coalesced vecBT loads, conflict-free STS ----
    // lt strides by 96 over 64*24 float4 slots; since 96 = 4*24,
    // j4 is loop-invariant and m advances by 4 per iteration.
    {
        const int j4 = lt % 24;             // float4 column group (invariant)
        const int m0 = lt / 24;             // starting hidden channel
        const int jb = 4*j4;
        const int n0i = nmsH[jb+0], n1i = nmsH[jb+1];
        const int n2i = nmsH[jb+2], n3i = nmsH[jb+3];
        const int anyMatch = n0i | n1i | n2i | n3i;
        const float4* vBT4 = (const float4*)(g_vecBT + (size_t)g*(HID*NPG));
        const float*  AuH  = Au_s + h*64;
        #pragma unroll 4
        for (int m = m0; m < 64; m += 4) {
            float4 v = vBT4[m*24 + j4];
            float  au = AuH[m];
            v.x += au; v.y += au; v.z += au; v.w += au;
            if (anyMatch) {
                float* vc = &v.x;
                #pragma unroll
                for (int c = 0; c < 4; c++) {
                    int j  = jb + c;
                    int nm = nmsH[j];
                    if (nm == 0) continue;
                    if (nm <= 2) {
                        vc[c] += g_Ce[(size_t)e0sH[j]*HID + m];
                        if (nm == 2) vc[c] += g_Ce[(size_t)e1sH[j]*HID + m];
                    } else {
                        for (int q = 0; q < ec; q++) {
                            long long pk = el[q];
                            if ((int)(pk & 0xffffffffLL) == j)
                                vc[c] += g_Ce[(size_t)((int)(pk >> 32))*HID + m];
                        }
                    }
                }
            }
            v.x = fmaxf(v.x, 0.f);
            v.y = fmaxf(v.y, 0.f);
            v.z = fmaxf(v.z, 0.f);
            v.w = fmaxf(v.w, 0.f);
            *(float4*)(H0h + m*96 + jb) = v;   // lanes consecutive -> no conflicts
        }
    }
    __syncthreads();

    // ---- GEMM: thread (jt,kt) computes h1[jt*8..+8][kt*8..+8], prefetched ----
    const int jt = lt >> 3;      // 0..11
    const int kt = lt & 7;       // 0..7
    float4 acc[8][2];
    #pragma unroll
    for (int a = 0; a < 8; a++) {
        acc[a][0] = make_float4(0.f, 0.f, 0.f, 0.f);
        acc[a][1] = make_float4(0.f, 0.f, 0.f, 0.f);
    }

    const float* Abase = H0h + jt*8;
    const float* Bbase = W2s + kt*8;
    float4 a0 = *(const float4*)(Abase);
    float4 a1 = *(const float4*)(Abase + 4);
    float4 b0 = *(const float4*)(Bbase);
    float4 b1 = *(const float4*)(Bbase + 4);
    #pragma unroll 4
    for (int m = 0; m < 64; m++) {
        float4 ca0 = a0, ca1 = a1, cb0 = b0, cb1 = b1;
        if (m < 63) {
            a0 = *(const float4*)(Abase + (m+1)*96);
            a1 = *(const float4*)(Abase + (m+1)*96 + 4);
            b0 = *(const float4*)(Bbase + (m+1)*W2PITCH);
            b1 = *(const float4*)(Bbase + (m+1)*W2PITCH + 4);
        }
        FMA4(acc[0][0], ca0.x, cb0); FMA4(acc[0][1], ca0.x, cb1);
        FMA4(acc[1][0], ca0.y, cb0); FMA4(acc[1][1], ca0.y, cb1);
        FMA4(acc[2][0], ca0.z, cb0); FMA4(acc[2][1], ca0.z, cb1);
        FMA4(acc[3][0], ca0.w, cb0); FMA4(acc[3][1], ca0.w, cb1);
        FMA4(acc[4][0], ca1.x, cb0); FMA4(acc[4][1], ca1.x, cb1);
        FMA4(acc[5][0], ca1.y, cb0); FMA4(acc[5][1], ca1.y, cb1);
        FMA4(acc[6][0], ca1.z, cb0); FMA4(acc[6][1], ca1.z, cb1);
        FMA4(acc[7][0], ca1.w, cb0); FMA4(acc[7][1], ca1.w, cb1);
    }

    // ---- epilogue: relu(h1+b2)*W3 partial, shuffle-reduce over kt lanes ----
    float po[8];
    {
        float4 bb0 = *(const float4*)(b2s + kt*8);
        float4 bb1 = *(const float4*)(b2s + kt*8 + 4);
        float4 ww0 = *(const float4*)(W3s + kt*8);
        float4 ww1 = *(const float4*)(W3s + kt*8 + 4);
        #pragma unroll
        for (int a = 0; a < 8; a++) {
            float p = 0.f;
            p = fmaf(fmaxf(acc[a][0].x + bb0.x, 0.f), ww0.x, p);
            p = fmaf(fmaxf(acc[a][0].y + bb0.y, 0.f), ww0.y, p);
            p = fmaf(fmaxf(acc[a][0].z + bb0.z, 0.f), ww0.z, p);
            p = fmaf(fmaxf(acc[a][0].w + bb0.w, 0.f), ww0.w, p);
            p = fmaf(fmaxf(acc[a][1].x + bb1.x, 0.f), ww1.x, p);
            p = fmaf(fmaxf(acc[a][1].y + bb1.y, 0.f), ww1.y, p);
            p = fmaf(fmaxf(acc[a][1].z + bb1.z, 0.f), ww1.z, p);
            p = fmaf(fmaxf(acc[a][1].w + bb1.w, 0.f), ww1.w, p);
            po[a] = p;
        }
    }
    #pragma unroll
    for (int ofs = 4; ofs > 0; ofs >>= 1)
        #pragma unroll
        for (int a = 0; a < 8; a++)
            po[a] += __shfl_xor_sync(0xffffffffu, po[a], ofs, 8);

    if (kt == 0) {
        float bias = b3[0];
        float4 o0 = make_float4(po[0]+bias, po[1]+bias, po[2]+bias, po[3]+bias);
        float4 o1 = make_float4(po[4]+bias, po[5]+bias, po[6]+bias, po[7]+bias);
        float* op = out + (size_t)g*(NPG*NPG) + (size_t)lu*NPG + jt*8;
        *(float4*)op       = o0;
        *(float4*)(op + 4) = o1;
    }
}

// ---------------- launch -----------------------------------------------------
extern "C" void kernel_launch(void* const* d_in, const int* in_sizes, int n_in,
                              void* d_out, int out_size)
{
    const float* x          = (const float*)d_in[0];
    const float* edge_attr  = (const float*)d_in[1];
    const int*   edge_index = (const int*)  d_in[2];

    int w = 6;
    if (n_in >= 6 && in_sizes[5] != 1) w = 5;
    if (n_in == 19) w = 5;
    const float* W_atom = (const float*)d_in[w+0];
    const float* b_atom = (const float*)d_in[w+1];
    const float* W_bond = (const float*)d_in[w+2];
    const float* b_bond = (const float*)d_in[w+3];
    const float* W_node = (const float*)d_in[w+4];
    const float* b_node = (const float*)d_in[w+5];
    const float* W_edge = (const float*)d_in[w+6];
    const float* b_edge = (const float*)d_in[w+7];
    const float* W1     = (const float*)d_in[w+8];
    const float* b1     = (const float*)d_in[w+9];
    const float* W2     = (const float*)d_in[w+10];
    const float* b2     = (const float*)d_in[w+11];
    const float* W3     = (const float*)d_in[w+12];
    const float* b3     = (const float*)d_in[w+13];

    const int smem_bytes = (2*64*96 + 64*W2PITCH + 128 + 64 + 64) * (int)sizeof(float)
                           + 2*96*(int)sizeof(long long)
                           + (3*2*96 + 2) * (int)sizeof(int);
    cudaFuncSetAttribute(pair_kernel, cudaFuncAttributeMaxDynamicSharedMemorySize, smem_bytes);

    const int P1 = INF*HID + EF*HID + 2*HID;            // 3200
    const int P2 = 2*INF*HID + EF*HID + HID;            // 5184
    prep1_kernel<<<(P1 + 255)/256, 256>>>(W_atom, b_atom, W_bond, b_bond,
                                          W_node, b_node, W_edge, b_edge);
    prep2_kernel<<<(P2 + 255)/256, 256>>>(W1, b1);
    encode_kernel<<<NODE_BLOCKS + EDGE_BLOCKS, 256>>>(x, edge_attr);
    pair_kernel<<<NODES/2, 192, smem_bytes>>>(edge_index, W2, b2, W3, b3, (float*)d_out);
}

// round 10
// speedup vs baseline: 1.1874x; 1.1874x over previous
#include <cuda_runtime.h>

// Problem constants (fixed by the reference generator)
#define NGR   64
#define NPG   96
#define NODES (NGR*NPG)       // 6144
#define HID   64
#define INF   32
#define EF    16
#define DEG   8
#define EDGES (NODES*DEG)     // 49152
#define EPG   (NPG*DEG)       // 768
#define PAIRS (NODES*NPG)     // 589824

// ---------------- scratch (static device globals) ---------------------------
__device__ float g_M1[INF*HID];
__device__ float g_M2[EF*HID];
__device__ float g_bn[HID];
__device__ float g_be[HID];
__device__ float g_WA[INF*HID];
__device__ float g_WB[INF*HID];
__device__ float g_WC[EF*HID];
__device__ float g_biasA[HID];
__device__ float g_biasB[HID];
__device__ float g_biasC[HID];
__device__ float g_vecA[NODES*HID];
__device__ float g_vecBT[NGR*HID*NPG];   // [graph][m][j]  m-major transposed
__device__ float g_Ce[(size_t)EDGES*HID];

// ---------------- K1a: first composition stage (parallel) -------------------
__global__ void prep1_kernel(const float* __restrict__ W_atom, const float* __restrict__ b_atom,
                             const float* __restrict__ W_bond, const float* __restrict__ b_bond,
                             const float* __restrict__ W_node, const float* __restrict__ b_node,
                             const float* __restrict__ W_edge, const float* __restrict__ b_edge)
{
    int i = blockIdx.x * blockDim.x + threadIdx.x;
    if (i < INF*HID) {
        int r = i >> 6, k = i & 63;
        float s = 0.f;
        #pragma unroll 8
        for (int j = 0; j < HID; j++) s = fmaf(W_atom[r*HID+j], W_node[j*HID+k], s);
        g_M1[i] = s;
    } else if (i < INF*HID + EF*HID) {
        int i2 = i - INF*HID;
        int r = i2 >> 6, k = i2 & 63;
        float s = 0.f;
        #pragma unroll 8
        for (int j = 0; j < HID; j++) s = fmaf(W_bond[r*HID+j], W_edge[j*HID+k], s);
        g_M2[i2] = s;
    } else if (i < INF*HID + EF*HID + HID) {
        int k = i - (INF*HID + EF*HID);
        float s = b_node[k];
        #pragma unroll 8
        for (int j = 0; j < HID; j++) s = fmaf(b_atom[j], W_node[j*HID+k], s);
        g_bn[k] = s;
    } else if (i < INF*HID + EF*HID + 2*HID) {
        int k = i - (INF*HID + EF*HID + HID);
        float s = b_edge[k];
        #pragma unroll 8
        for (int j = 0; j < HID; j++) s = fmaf(b_bond[j], W_edge[j*HID+k], s);
        g_be[k] = s;
    }
}

// ---------------- K1b: fold into W1 blocks (parallel) ------------------------
__global__ void prep2_kernel(const float* __restrict__ W1, const float* __restrict__ b1)
{
    int i = blockIdx.x * blockDim.x + threadIdx.x;
    if (i < INF*HID) {
        int r = i >> 6, k = i & 63;
        float s = 0.f;
        #pragma unroll 8
        for (int j = 0; j < HID; j++) s = fmaf(g_M1[r*HID+j], W1[j*HID + k], s);
        g_WA[i] = s;
    } else if (i < 2*INF*HID) {
        int i2 = i - INF*HID;
        int r = i2 >> 6, k = i2 & 63;
        float s = 0.f;
        #pragma unroll 8
        for (int j = 0; j < HID; j++) s = fmaf(g_M1[r*HID+j], W1[(64+j)*HID + k], s);
        g_WB[i2] = s;
    } else if (i < 2*INF*HID + EF*HID) {
        int i2 = i - 2*INF*HID;
        int r = i2 >> 6, k = i2 & 63;
        float s = 0.f;
        #pragma unroll 8
        for (int j = 0; j < HID; j++) s = fmaf(g_M2[r*HID+j], W1[(128+j)*HID + k], s);
        g_WC[i2] = s;
    } else if (i < 2*INF*HID + EF*HID + HID) {
        int k = i - (2*INF*HID + EF*HID);
        float sa = b1[k], sb = 0.f, sc = 0.f;
        #pragma unroll 4
        for (int j = 0; j < HID; j++) {
            sa = fmaf(g_bn[j], W1[j*HID + k], sa);
            sb = fmaf(g_bn[j], W1[(64+j)*HID + k], sb);
            sc = fmaf(g_be[j], W1[(128+j)*HID + k], sc);
        }
        g_biasA[k] = sa;
        g_biasB[k] = sb;
        g_biasC[k] = sc;
    }
}

// ---------------- K2: fused per-node + per-edge layer-1 partials -------------
#define NODE_BLOCKS (NODES/2)
#define EDGE_BLOCKS (EDGES/4)
__global__ void encode_kernel(const float* __restrict__ x, const float* __restrict__ ea)
{
    if (blockIdx.x < NODE_BLOCKS) {
        __shared__ float xr[2][INF];
        int half = threadIdx.x >> 7;
        int t    = threadIdx.x & 127;
        int node = blockIdx.x*2 + half;
        if (t < INF) xr[half][t] = x[node*INF + t];
        __syncthreads();
        int k = t & 63;
        const float* W = (t < 64) ? g_WA : g_WB;
        float s = (t < 64) ? g_biasA[k] : g_biasB[k];
        #pragma unroll
        for (int f = 0; f < INF; f++) s = fmaf(xr[half][f], W[f*HID + k], s);
        if (t < 64) {
            g_vecA[node*HID + k] = s;
        } else {
            int gg = node / NPG, lj = node - gg*NPG;
            g_vecBT[gg*(HID*NPG) + k*NPG + lj] = s;     // transposed store
        }
    } else {
        __shared__ float er[4][EF];
        int b   = blockIdx.x - NODE_BLOCKS;
        int grp = threadIdx.x >> 6;
        int k   = threadIdx.x & 63;
        int e   = b * 4 + grp;
        if (k < EF) er[grp][k] = ea[e*EF + k];
        __syncthreads();
        float s = g_biasC[k];
        #pragma unroll
        for (int f = 0; f < EF; f++) s = fmaf(er[grp][f], g_WC[f*HID + k], s);
        g_Ce[(size_t)e*HID + k] = s;
    }
}

// ---------------- K3: fused pairwise MLP, register-tiled GEMM ---------------
#define W2PITCH 72

#define FMA4(acc, a, b) \
    acc.x = fmaf(a, b.x, acc.x); \
    acc.y = fmaf(a, b.y, acc.y); \
    acc.z = fmaf(a, b.z, acc.z); \
    acc.w = fmaf(a, b.w, acc.w);

__global__ void __launch_bounds__(192, 3)
pair_kernel(const int* __restrict__ edge_index,
            const float* __restrict__ W2, const float* __restrict__ b2,
            const float* __restrict__ W3, const float* __restrict__ b3,
            float* __restrict__ out)
{
    extern __shared__ float s[];
    float* H0   = s;                         // [2][64][96]
    float* W2s  = s + 2*64*96;               // [64][72]
    float* Au_s = W2s + 64*W2PITCH;          // [2][64]
    float* W3s  = Au_s + 128;                // [64]
    float* b2s  = W3s + 64;                  // [64]
    long long* elist = (long long*)(b2s + 64);   // [2][96]
    int* ecount = (int*)(elist + 2*96);          // [2]

    const int tid = threadIdx.x;
    const int h   = tid / 96;
    const int lt  = tid - h*96;
    const int u   = blockIdx.x*2 + h;
    const int g   = u / NPG;
    const int lu  = u - g*NPG;
    float* H0h = H0 + h*64*96;
    long long* el = elist + h*96;

    if (lt == 0) ecount[h] = 0;
    for (int idx = tid; idx < 64*64; idx += 192) {
        int m = idx >> 6, k = idx & 63;
        W2s[m*W2PITCH + k] = W2[idx];
    }
    if (tid < 64) { W3s[tid] = W3[tid]; b2s[tid] = b2[tid]; }
    if (lt < 64) Au_s[h*64 + lt] = g_vecA[(size_t)u*HID + lt];
    __syncthreads();

    // gather this node's out-edges
    const int* srcA = edge_index;
    const int* dstA = edge_index + EDGES;
    for (int e = g*EPG + lt; e < (g+1)*EPG; e += 96) {
        if (srcA[e] == u) {
            int p = atomicAdd(&ecount[h], 1);
            if (p < 96) el[p] = ((long long)e << 32) | (unsigned)(dstA[e] - g*NPG);
        }
    }
    __syncthreads();
    const int ec = min(ecount[h], 96);
    if (lt == 0) {      // deterministic order
        for (int a = 1; a < ec; a++) {
            long long v = el[a]; int b = a - 1;
            while (b >= 0 && el[b] > v) { el[b+1] = el[b]; b--; }
            el[b+1] = v;
        }
    }
    __syncthreads();

    // ---- Phase A: branch-free coalesced build (no edge handling) ----
    // j4 = lt%24 invariant; m advances by 4. LDG.128 coalesced, STS.128
    // conflict-free. Stores relu(vecBT + Au).
    const float* vBTg = g_vecBT + (size_t)g*(HID*NPG);
    {
        const int j4 = lt % 24;
        const int m0 = lt / 24;
        const int jb = 4*j4;
        const float4* vBT4 = (const float4*)vBTg;
        const float*  AuH  = Au_s + h*64;
        #pragma unroll 4
        for (int m = m0; m < 64; m += 4) {
            float4 v = vBT4[m*24 + j4];
            float  au = AuH[m];
            v.x = fmaxf(v.x + au, 0.f);
            v.y = fmaxf(v.y + au, 0.f);
            v.z = fmaxf(v.z + au, 0.f);
            v.w = fmaxf(v.w + au, 0.f);
            *(float4*)(H0h + m*96 + jb) = v;
        }
    }
    __syncthreads();

    // ---- Phase B: recompute edge-bearing columns only (owner thread j=lt) ----
    {
        int e0 = -1, e1 = -1, nm = 0;
        for (int q = 0; q < ec; q++) {
            long long pk = el[q];
            if ((int)(pk & 0xffffffffLL) == lt) {
                int e = (int)(pk >> 32);
                if (nm == 0) e0 = e; else if (nm == 1) e1 = e;
                nm++;
            }
        }
        if (nm > 0) {
            const float* AuH = Au_s + h*64;
            const int j = lt;
            if (nm <= 2) {
                const float* ce0 = g_Ce + (size_t)e0*HID;
                const float* ce1 = (nm == 2) ? (g_Ce + (size_t)e1*HID) : 0;
                #pragma unroll 8
                for (int m = 0; m < 64; m++) {
                    float v = vBTg[m*NPG + j] + AuH[m] + ce0[m];
                    if (ce1) v += ce1[m];
                    H0h[m*96 + j] = fmaxf(v, 0.f);
                }
            } else {
                for (int m = 0; m < 64; m++) {
                    float v = vBTg[m*NPG + j] + AuH[m];
                    for (int q = 0; q < ec; q++) {
                        long long pk = el[q];
                        if ((int)(pk & 0xffffffffLL) == j)
                            v += g_Ce[(size_t)((int)(pk >> 32))*HID + m];
                    }
                    H0h[m*96 + j] = fmaxf(v, 0.f);
                }
            }
        }
    }
    __syncthreads();

    // ---- GEMM: thread (jt,kt) computes h1[jt*8..+8][kt*8..+8] (R5 loop) ----
    const int jt = lt >> 3;      // 0..11
    const int kt = lt & 7;       // 0..7
    float4 acc[8][2];
    #pragma unroll
    for (int a = 0; a < 8; a++) {
        acc[a][0] = make_float4(0.f, 0.f, 0.f, 0.f);
        acc[a][1] = make_float4(0.f, 0.f, 0.f, 0.f);
    }

    const float* Abase = H0h + jt*8;
    const float* Bbase = W2s + kt*8;
    #pragma unroll 4
    for (int m = 0; m < 64; m++) {
        float4 a0 = *(const float4*)(Abase + m*96);
        float4 a1 = *(const float4*)(Abase + m*96 + 4);
        float4 b0 = *(const float4*)(Bbase + m*W2PITCH);
        float4 b1 = *(const float4*)(Bbase + m*W2PITCH + 4);
        FMA4(acc[0][0], a0.x, b0); FMA4(acc[0][1], a0.x, b1);
        FMA4(acc[1][0], a0.y, b0); FMA4(acc[1][1], a0.y, b1);
        FMA4(acc[2][0], a0.z, b0); FMA4(acc[2][1], a0.z, b1);
        FMA4(acc[3][0], a0.w, b0); FMA4(acc[3][1], a0.w, b1);
        FMA4(acc[4][0], a1.x, b0); FMA4(acc[4][1], a1.x, b1);
        FMA4(acc[5][0], a1.y, b0); FMA4(acc[5][1], a1.y, b1);
        FMA4(acc[6][0], a1.z, b0); FMA4(acc[6][1], a1.z, b1);
        FMA4(acc[7][0], a1.w, b0); FMA4(acc[7][1], a1.w, b1);
    }

    // ---- epilogue: relu(h1+b2)*W3 partial, shuffle-reduce over kt lanes ----
    float po[8];
    {
        float4 bb0 = *(const float4*)(b2s + kt*8);
        float4 bb1 = *(const float4*)(b2s + kt*8 + 4);
        float4 ww0 = *(const float4*)(W3s + kt*8);
        float4 ww1 = *(const float4*)(W3s + kt*8 + 4);
        #pragma unroll
        for (int a = 0; a < 8; a++) {
            float p = 0.f;
            p = fmaf(fmaxf(acc[a][0].x + bb0.x, 0.f), ww0.x, p);
            p = fmaf(fmaxf(acc[a][0].y + bb0.y, 0.f), ww0.y, p);
            p = fmaf(fmaxf(acc[a][0].z + bb0.z, 0.f), ww0.z, p);
            p = fmaf(fmaxf(acc[a][0].w + bb0.w, 0.f), ww0.w, p);
            p = fmaf(fmaxf(acc[a][1].x + bb1.x, 0.f), ww1.x, p);
            p = fmaf(fmaxf(acc[a][1].y + bb1.y, 0.f), ww1.y, p);
            p = fmaf(fmaxf(acc[a][1].z + bb1.z, 0.f), ww1.z, p);
            p = fmaf(fmaxf(acc[a][1].w + bb1.w, 0.f), ww1.w, p);
            po[a] = p;
        }
    }
    #pragma unroll
    for (int ofs = 4; ofs > 0; ofs >>= 1)
        #pragma unroll
        for (int a = 0; a < 8; a++)
            po[a] += __shfl_xor_sync(0xffffffffu, po[a], ofs, 8);

    if (kt == 0) {
        float bias = b3[0];
        float4 o0 = make_float4(po[0]+bias, po[1]+bias, po[2]+bias, po[3]+bias);
        float4 o1 = make_float4(po[4]+bias, po[5]+bias, po[6]+bias, po[7]+bias);
        float* op = out + (size_t)g*(NPG*NPG) + (size_t)lu*NPG + jt*8;
        *(float4*)op       = o0;
        *(float4*)(op + 4) = o1;
    }
}

// ---------------- launch -----------------------------------------------------
extern "C" void kernel_launch(void* const* d_in, const int* in_sizes, int n_in,
                              void* d_out, int out_size)
{
    const float* x          = (const float*)d_in[0];
    const float* edge_attr  = (const float*)d_in[1];
    const int*   edge_index = (const int*)  d_in[2];

    int w = 6;
    if (n_in >= 6 && in_sizes[5] != 1) w = 5;
    if (n_in == 19) w = 5;
    const float* W_atom = (const float*)d_in[w+0];
    const float* b_atom = (const float*)d_in[w+1];
    const float* W_bond = (const float*)d_in[w+2];
    const float* b_bond = (const float*)d_in[w+3];
    const float* W_node = (const float*)d_in[w+4];
    const float* b_node = (const float*)d_in[w+5];
    const float* W_edge = (const float*)d_in[w+6];
    const float* b_edge = (const float*)d_in[w+7];
    const float* W1     = (const float*)d_in[w+8];
    const float* b1     = (const float*)d_in[w+9];
    const float* W2     = (const float*)d_in[w+10];
    const float* b2     = (const float*)d_in[w+11];
    const float* W3     = (const float*)d_in[w+12];
    const float* b3     = (const float*)d_in[w+13];

    const int smem_bytes = (2*64*96 + 64*W2PITCH + 128 + 64 + 64) * (int)sizeof(float)
                           + 2*96*(int)sizeof(long long) + 2*(int)sizeof(int);
    cudaFuncSetAttribute(pair_kernel, cudaFuncAttributeMaxDynamicSharedMemorySize, smem_bytes);

    const int P1 = INF*HID + EF*HID + 2*HID;            // 3200
    const int P2 = 2*INF*HID + EF*HID + HID;            // 5184
    prep1_kernel<<<(P1 + 255)/256, 256>>>(W_atom, b_atom, W_bond, b_bond,
                                          W_node, b_node, W_edge, b_edge);
    prep2_kernel<<<(P2 + 255)/256, 256>>>(W1, b1);
    encode_kernel<<<NODE_BLOCKS + EDGE_BLOCKS, 256>>>(x, edge_attr);
    pair_kernel<<<NODES/2, 192, smem_bytes>>>(edge_index, W2, b2, W3, b3, (float*)d_out);
}

// round 12
// speedup vs baseline: 1.2794x; 1.0775x over previous
#include <cuda_runtime.h>

// Problem constants (fixed by the reference generator)
#define NGR   64
#define NPG   96
#define NODES (NGR*NPG)       // 6144
#define HID   64
#define INF   32
#define EF    16
#define DEG   8
#define EDGES (NODES*DEG)     // 49152
#define EPG   (NPG*DEG)       // 768
#define PAIRS (NODES*NPG)     // 589824

// ---------------- scratch (static device globals) ---------------------------
__device__ float g_M1[INF*HID];
__device__ float g_M2[EF*HID];
__device__ float g_bn[HID];
__device__ float g_be[HID];
__device__ float g_WA[INF*HID];
__device__ float g_WB[INF*HID];
__device__ float g_WC[EF*HID];
__device__ float g_biasA[HID];
__device__ float g_biasB[HID];
__device__ float g_biasC[HID];
__device__ float g_vecA[NODES*HID];
__device__ float g_vecBT[NGR*HID*NPG];   // [graph][m][j]  m-major transposed
__device__ float g_Ce[(size_t)EDGES*HID];

// ---------------- K1a: first composition stage (parallel) -------------------
__global__ void prep1_kernel(const float* __restrict__ W_atom, const float* __restrict__ b_atom,
                             const float* __restrict__ W_bond, const float* __restrict__ b_bond,
                             const float* __restrict__ W_node, const float* __restrict__ b_node,
                             const float* __restrict__ W_edge, const float* __restrict__ b_edge)
{
    int i = blockIdx.x * blockDim.x + threadIdx.x;
    if (i < INF*HID) {
        int r = i >> 6, k = i & 63;
        float s = 0.f;
        #pragma unroll 8
        for (int j = 0; j < HID; j++) s = fmaf(W_atom[r*HID+j], W_node[j*HID+k], s);
        g_M1[i] = s;
    } else if (i < INF*HID + EF*HID) {
        int i2 = i - INF*HID;
        int r = i2 >> 6, k = i2 & 63;
        float s = 0.f;
        #pragma unroll 8
        for (int j = 0; j < HID; j++) s = fmaf(W_bond[r*HID+j], W_edge[j*HID+k], s);
        g_M2[i2] = s;
    } else if (i < INF*HID + EF*HID + HID) {
        int k = i - (INF*HID + EF*HID);
        float s = b_node[k];
        #pragma unroll 8
        for (int j = 0; j < HID; j++) s = fmaf(b_atom[j], W_node[j*HID+k], s);
        g_bn[k] = s;
    } else if (i < INF*HID + EF*HID + 2*HID) {
        int k = i - (INF*HID + EF*HID + HID);
        float s = b_edge[k];
        #pragma unroll 8
        for (int j = 0; j < HID; j++) s = fmaf(b_bond[j], W_edge[j*HID+k], s);
        g_be[k] = s;
    }
}

// ---------------- K1b: fold into W1 blocks (parallel) ------------------------
__global__ void prep2_kernel(const float* __restrict__ W1, const float* __restrict__ b1)
{
    int i = blockIdx.x * blockDim.x + threadIdx.x;
    if (i < INF*HID) {
        int r = i >> 6, k = i & 63;
        float s = 0.f;
        #pragma unroll 8
        for (int j = 0; j < HID; j++) s = fmaf(g_M1[r*HID+j], W1[j*HID + k], s);
        g_WA[i] = s;
    } else if (i < 2*INF*HID) {
        int i2 = i - INF*HID;
        int r = i2 >> 6, k = i2 & 63;
        float s = 0.f;
        #pragma unroll 8
        for (int j = 0; j < HID; j++) s = fmaf(g_M1[r*HID+j], W1[(64+j)*HID + k], s);
        g_WB[i2] = s;
    } else if (i < 2*INF*HID + EF*HID) {
        int i2 = i - 2*INF*HID;
        int r = i2 >> 6, k = i2 & 63;
        float s = 0.f;
        #pragma unroll 8
        for (int j = 0; j < HID; j++) s = fmaf(g_M2[r*HID+j], W1[(128+j)*HID + k], s);
        g_WC[i2] = s;
    } else if (i < 2*INF*HID + EF*HID + HID) {
        int k = i - (2*INF*HID + EF*HID);
        float sa = b1[k], sb = 0.f, sc = 0.f;
        #pragma unroll 4
        for (int j = 0; j < HID; j++) {
            sa = fmaf(g_bn[j], W1[j*HID + k], sa);
            sb = fmaf(g_bn[j], W1[(64+j)*HID + k], sb);
            sc = fmaf(g_be[j], W1[(128+j)*HID + k], sc);
        }
        g_biasA[k] = sa;
        g_biasB[k] = sb;
        g_biasC[k] = sc;
    }
}

// ---------------- K2: fused per-node + per-edge layer-1 partials -------------
#define NODE_BLOCKS (NODES/2)
#define EDGE_BLOCKS (EDGES/4)
__global__ void encode_kernel(const float* __restrict__ x, const float* __restrict__ ea)
{
    if (blockIdx.x < NODE_BLOCKS) {
        __shared__ float xr[2][INF];
        int half = threadIdx.x >> 7;
        int t    = threadIdx.x & 127;
        int node = blockIdx.x*2 + half;
        if (t < INF) xr[half][t] = x[node*INF + t];
        __syncthreads();
        int k = t & 63;
        const float* W = (t < 64) ? g_WA : g_WB;
        float s = (t < 64) ? g_biasA[k] : g_biasB[k];
        #pragma unroll
        for (int f = 0; f < INF; f++) s = fmaf(xr[half][f], W[f*HID + k], s);
        if (t < 64) {
            g_vecA[node*HID + k] = s;
        } else {
            int gg = node / NPG, lj = node - gg*NPG;
            g_vecBT[gg*(HID*NPG) + k*NPG + lj] = s;     // transposed store
        }
    } else {
        __shared__ float er[4][EF];
        int b   = blockIdx.x - NODE_BLOCKS;
        int grp = threadIdx.x >> 6;
        int k   = threadIdx.x & 63;
        int e   = b * 4 + grp;
        if (k < EF) er[grp][k] = ea[e*EF + k];
        __syncthreads();
        float s = g_biasC[k];
        #pragma unroll
        for (int f = 0; f < EF; f++) s = fmaf(er[grp][f], g_WC[f*HID + k], s);
        g_Ce[(size_t)e*HID + k] = s;
    }
}

// ---------------- K3: fused pairwise MLP, register-tiled GEMM ---------------
#define W2PITCH 72

#define FMA4(acc, a, b) \
    acc.x = fmaf(a, b.x, acc.x); \
    acc.y = fmaf(a, b.y, acc.y); \
    acc.z = fmaf(a, b.z, acc.z); \
    acc.w = fmaf(a, b.w, acc.w);

__global__ void __launch_bounds__(192, 3)
pair_kernel(const int* __restrict__ edge_index,
            const float* __restrict__ W2, const float* __restrict__ b2,
            const float* __restrict__ W3, const float* __restrict__ b3,
            float* __restrict__ out)
{
    extern __shared__ float s[];
    float* H0   = s;                         // [2][64][96]
    float* W2s  = s + 2*64*96;               // [64][72]
    float* Au_s = W2s + 64*W2PITCH;          // [2][64]
    float* W3s  = Au_s + 128;                // [64]
    float* b2s  = W3s + 64;                  // [64]
    long long* elist = (long long*)(b2s + 64);   // [2][96]
    int* e0s    = (int*)(elist + 2*96);          // [2][96]
    int* e1s    = e0s + 2*96;                    // [2][96]
    int* nms    = e1s + 2*96;                    // [2][96]
    int* ecount = nms + 2*96;                    // [2]

    const int tid = threadIdx.x;
    const int h   = tid / 96;
    const int lt  = tid - h*96;
    const int u   = blockIdx.x*2 + h;
    const int g   = u / NPG;
    const int lu  = u - g*NPG;
    float* H0h = H0 + h*64*96;
    long long* el = elist + h*96;
    int* e0sH = e0s + h*96;
    int* e1sH = e1s + h*96;
    int* nmsH = nms + h*96;

    if (lt == 0) ecount[h] = 0;
    for (int idx = tid; idx < 64*64; idx += 192) {
        int m = idx >> 6, k = idx & 63;
        W2s[m*W2PITCH + k] = W2[idx];
    }
    if (tid < 64) { W3s[tid] = W3[tid]; b2s[tid] = b2[tid]; }
    if (lt < 64) Au_s[h*64 + lt] = g_vecA[(size_t)u*HID + lt];
    __syncthreads();

    // gather this node's out-edges
    const int* srcA = edge_index;
    const int* dstA = edge_index + EDGES;
    for (int e = g*EPG + lt; e < (g+1)*EPG; e += 96) {
        if (srcA[e] == u) {
            int p = atomicAdd(&ecount[h], 1);
            if (p < 96) el[p] = ((long long)e << 32) | (unsigned)(dstA[e] - g*NPG);
        }
    }
    __syncthreads();
    const int ec = min(ecount[h], 96);
    if (lt == 0) {      // deterministic order
        for (int a = 1; a < ec; a++) {
            long long v = el[a]; int b = a - 1;
            while (b >= 0 && el[b] > v) { el[b+1] = el[b]; b--; }
            el[b+1] = v;
        }
    }
    __syncthreads();

    // per-column edge-match table (thread lt owns column j = lt)
    {
        int e0 = -1, e1 = -1, nm = 0;
        for (int q = 0; q < ec; q++) {
            long long pk = el[q];
            if ((int)(pk & 0xffffffffLL) == lt) {
                int e = (int)(pk >> 32);
                if (nm == 0) e0 = e; else if (nm == 1) e1 = e;
                nm++;
            }
        }
        e0sH[lt] = e0;
        e1sH[lt] = e1;
        nmsH[lt] = nm;
    }
    __syncthreads();

    // ---- Phase A: branch-free coalesced build ----
    // Clean columns get relu applied; edge-bearing columns stored pre-relu
    // (select per component). Coalesced LDG.128, conflict-free STS.128.
    const float* vBTg = g_vecBT + (size_t)g*(HID*NPG);
    {
        const int j4 = lt % 24;
        const int m0 = lt / 24;
        const int jb = 4*j4;
        // per-thread invariant: does each of my 4 columns carry edges?
        const bool c0 = (nmsH[jb+0] != 0);
        const bool c1 = (nmsH[jb+1] != 0);
        const bool c2 = (nmsH[jb+2] != 0);
        const bool c3 = (nmsH[jb+3] != 0);
        const float4* vBT4 = (const float4*)vBTg;
        const float*  AuH  = Au_s + h*64;
        #pragma unroll 4
        for (int m = m0; m < 64; m += 4) {
            float4 v = vBT4[m*24 + j4];
            float  au = AuH[m];
            v.x += au; v.y += au; v.z += au; v.w += au;
            // relu only for clean columns (SEL, no branch)
            v.x = c0 ? v.x : fmaxf(v.x, 0.f);
            v.y = c1 ? v.y : fmaxf(v.y, 0.f);
            v.z = c2 ? v.z : fmaxf(v.z, 0.f);
            v.w = c3 ? v.w : fmaxf(v.w, 0.f);
            *(float4*)(H0h + m*96 + jb) = v;
        }
    }
    __syncthreads();

    // ---- Phase B: owner thread finishes edge-bearing columns from SMEM ----
    {
        const int nm = nmsH[lt];
        if (nm > 0) {
            const int j = lt;
            if (nm <= 2) {
                const float* ce0 = g_Ce + (size_t)e0sH[lt]*HID;
                const float* ce1 = (nm == 2) ? (g_Ce + (size_t)e1sH[lt]*HID) : 0;
                #pragma unroll 8
                for (int m = 0; m < 64; m++) {
                    float v = H0h[m*96 + j] + ce0[m];      // smem read, contiguous LDG
                    if (ce1) v += ce1[m];
                    H0h[m*96 + j] = fmaxf(v, 0.f);
                }
            } else {
                for (int m = 0; m < 64; m++) {
                    float v = H0h[m*96 + j];
                    for (int q = 0; q < ec; q++) {
                        long long pk = el[q];
                        if ((int)(pk & 0xffffffffLL) == j)
                            v += g_Ce[(size_t)((int)(pk >> 32))*HID + m];
                    }
                    H0h[m*96 + j] = fmaxf(v, 0.f);
                }
            }
        }
    }
    __syncthreads();

    // ---- GEMM: thread (jt,kt) computes h1[jt*8..+8][kt*8..+8] (R5 loop) ----
    const int jt = lt >> 3;      // 0..11
    const int kt = lt & 7;       // 0..7
    float4 acc[8][2];
    #pragma unroll
    for (int a = 0; a < 8; a++) {
        acc[a][0] = make_float4(0.f, 0.f, 0.f, 0.f);
        acc[a][1] = make_float4(0.f, 0.f, 0.f, 0.f);
    }

    const float* Abase = H0h + jt*8;
    const float* Bbase = W2s + kt*8;
    #pragma unroll 4
    for (int m = 0; m < 64; m++) {
        float4 a0 = *(const float4*)(Abase + m*96);
        float4 a1 = *(const float4*)(Abase + m*96 + 4);
        float4 b0 = *(const float4*)(Bbase + m*W2PITCH);
        float4 b1 = *(const float4*)(Bbase + m*W2PITCH + 4);
        FMA4(acc[0][0], a0.x, b0); FMA4(acc[0][1], a0.x, b1);
        FMA4(acc[1][0], a0.y, b0); FMA4(acc[1][1], a0.y, b1);
        FMA4(acc[2][0], a0.z, b0); FMA4(acc[2][1], a0.z, b1);
        FMA4(acc[3][0], a0.w, b0); FMA4(acc[3][1], a0.w, b1);
        FMA4(acc[4][0], a1.x, b0); FMA4(acc[4][1], a1.x, b1);
        FMA4(acc[5][0], a1.y, b0); FMA4(acc[5][1], a1.y, b1);
        FMA4(acc[6][0], a1.z, b0); FMA4(acc[6][1], a1.z, b1);
        FMA4(acc[7][0], a1.w, b0); FMA4(acc[7][1], a1.w, b1);
    }

    // ---- epilogue: relu(h1+b2)*W3 partial, shuffle-reduce over kt lanes ----
    float po[8];
    {
        float4 bb0 = *(const float4*)(b2s + kt*8);
        float4 bb1 = *(const float4*)(b2s + kt*8 + 4);
        float4 ww0 = *(const float4*)(W3s + kt*8);
        float4 ww1 = *(const float4*)(W3s + kt*8 + 4);
        #pragma unroll
        for (int a = 0; a < 8; a++) {
            float p = 0.f;
            p = fmaf(fmaxf(acc[a][0].x + bb0.x, 0.f), ww0.x, p);
            p = fmaf(fmaxf(acc[a][0].y + bb0.y, 0.f), ww0.y, p);
            p = fmaf(fmaxf(acc[a][0].z + bb0.z, 0.f), ww0.z, p);
            p = fmaf(fmaxf(acc[a][0].w + bb0.w, 0.f), ww0.w, p);
            p = fmaf(fmaxf(acc[a][1].x + bb1.x, 0.f), ww1.x, p);
            p = fmaf(fmaxf(acc[a][1].y + bb1.y, 0.f), ww1.y, p);
            p = fmaf(fmaxf(acc[a][1].z + bb1.z, 0.f), ww1.z, p);
            p = fmaf(fmaxf(acc[a][1].w + bb1.w, 0.f), ww1.w, p);
            po[a] = p;
        }
    }
    #pragma unroll
    for (int ofs = 4; ofs > 0; ofs >>= 1)
        #pragma unroll
        for (int a = 0; a < 8; a++)
            po[a] += __shfl_xor_sync(0xffffffffu, po[a], ofs, 8);

    if (kt == 0) {
        float bias = b3[0];
        float4 o0 = make_float4(po[0]+bias, po[1]+bias, po[2]+bias, po[3]+bias);
        float4 o1 = make_float4(po[4]+bias, po[5]+bias, po[6]+bias, po[7]+bias);
        float* op = out + (size_t)g*(NPG*NPG) + (size_t)lu*NPG + jt*8;
        *(float4*)op       = o0;
        *(float4*)(op + 4) = o1;
    }
}

// ---------------- launch -----------------------------------------------------
extern "C" void kernel_launch(void* const* d_in, const int* in_sizes, int n_in,
                              void* d_out, int out_size)
{
    const float* x          = (const float*)d_in[0];
    const float* edge_attr  = (const float*)d_in[1];
    const int*   edge_index = (const int*)  d_in[2];

    int w = 6;
    if (n_in >= 6 && in_sizes[5] != 1) w = 5;
    if (n_in == 19) w = 5;
    const float* W_atom = (const float*)d_in[w+0];
    const float* b_atom = (const float*)d_in[w+1];
    const float* W_bond = (const float*)d_in[w+2];
    const float* b_bond = (const float*)d_in[w+3];
    const float* W_node = (const float*)d_in[w+4];
    const float* b_node = (const float*)d_in[w+5];
    const float* W_edge = (const float*)d_in[w+6];
    const float* b_edge = (const float*)d_in[w+7];
    const float* W1     = (const float*)d_in[w+8];
    const float* b1     = (const float*)d_in[w+9];
    const float* W2     = (const float*)d_in[w+10];
    const float* b2     = (const float*)d_in[w+11];
    const float* W3     = (const float*)d_in[w+12];
    const float* b3     = (const float*)d_in[w+13];

    const int smem_bytes = (2*64*96 + 64*W2PITCH + 128 + 64 + 64) * (int)sizeof(float)
                           + 2*96*(int)sizeof(long long)
                           + (3*2*96 + 2) * (int)sizeof(int);
    cudaFuncSetAttribute(pair_kernel, cudaFuncAttributeMaxDynamicSharedMemorySize, smem_bytes);

    const int P1 = INF*HID + EF*HID + 2*HID;            // 3200
    const int P2 = 2*INF*HID + EF*HID + HID;            // 5184
    prep1_kernel<<<(P1 + 255)/256, 256>>>(W_atom, b_atom, W_bond, b_bond,
                                          W_node, b_node, W_edge, b_edge);
    prep2_kernel<<<(P2 + 255)/256, 256>>>(W1, b1);
    encode_kernel<<<NODE_BLOCKS + EDGE_BLOCKS, 256>>>(x, edge_attr);
    pair_kernel<<<NODES/2, 192, smem_bytes>>>(edge_index, W2, b2, W3, b3, (float*)d_out);
}